// round 4
// baseline (speedup 1.0000x reference)
#include <cuda_runtime.h>
#include <math.h>

#define BB 16
#define TT 4096
#define CC 8
#define FF 64
#define KW 11
#define LL 4096
#define TSEG 8

// Scratch (device globals; no runtime allocation). 16B-aligned: accessed as float4.
__device__ __align__(16) float g_A[BB * FF * TT];        // 16 MB: conv+BN -> softmax+posenc, [B][F][T]
__device__ __align__(16) float g_part[TSEG * BB * LL];   // 2 MB: partial T-sums of sigmoid(dense)

// ---------------- f32x2 packed helpers (sm_103a FFMA2) ----------------
__device__ __forceinline__ unsigned long long packff(float lo, float hi) {
    unsigned long long r;
    asm("mov.b64 %0, {%1, %2};" : "=l"(r) : "f"(lo), "f"(hi));
    return r;
}
__device__ __forceinline__ void unpackff(unsigned long long v, float& lo, float& hi) {
    asm("mov.b64 {%0, %1}, %2;" : "=f"(lo), "=f"(hi) : "l"(v));
}
__device__ __forceinline__ void ffma2(unsigned long long& d, unsigned long long a, unsigned long long b) {
    asm("fma.rn.f32x2 %0, %1, %2, %0;" : "+l"(d) : "l"(a), "l"(b));
}

// ---------------- Kernel 1: Conv1D (SAME) + BatchNorm -> g_A[b][f][t] ----------------
__global__ __launch_bounds__(256) void conv_bn_kernel(
    const float* __restrict__ x,        // [B,T,C]
    const float* __restrict__ conv_w,   // [K,C,F]
    const float* __restrict__ conv_b,   // [F]
    const float* __restrict__ gamma,
    const float* __restrict__ beta,
    const float* __restrict__ mean,
    const float* __restrict__ var)
{
    __shared__ __align__(16) float ws[KW * CC * FF];     // 5632 floats (float4-copied) — FIRST
    __shared__ __align__(16) float xs[266][9];           // halo tile, padded pitch

    const int tid = threadIdx.x;
    const int b  = blockIdx.y;
    const int t0 = blockIdx.x * 256;

    for (int i = tid; i < (KW * CC * FF) / 4; i += 256)
        ((float4*)ws)[i] = ((const float4*)conv_w)[i];

    for (int i = tid; i < 266; i += 256) {
        int t = t0 + i - 5;
        if (t >= 0 && t < TT) {
            const float* xp = x + ((size_t)b * TT + t) * CC;
            #pragma unroll
            for (int c = 0; c < CC; c++) xs[i][c] = xp[c];
        } else {
            #pragma unroll
            for (int c = 0; c < CC; c++) xs[i][c] = 0.f;
        }
    }
    __syncthreads();

    const int t = t0 + tid;
    for (int fo = 0; fo < FF; fo += 8) {
        float acc[8];
        #pragma unroll
        for (int j = 0; j < 8; j++) acc[j] = conv_b[fo + j];
        #pragma unroll
        for (int k = 0; k < KW; k++) {
            #pragma unroll
            for (int c = 0; c < CC; c++) {
                float xv = xs[tid + k][c];
                const float* wp = &ws[(k * CC + c) * FF + fo];
                #pragma unroll
                for (int j = 0; j < 8; j++) acc[j] = fmaf(xv, wp[j], acc[j]);
            }
        }
        #pragma unroll
        for (int j = 0; j < 8; j++) {
            int f = fo + j;
            float inv = rsqrtf(var[f] + 1e-3f);
            float val = (acc[j] - mean[f]) * inv * gamma[f] + beta[f];
            g_A[((size_t)b * FF + f) * TT + t] = val;
        }
    }
}

// ---------------- Kernel 2: softmax over T (per b,f) + sine positional encoding ----------------
__global__ __launch_bounds__(256) void softmax_pe_kernel()
{
    const int bf = blockIdx.x;           // b*64 + f
    const int f  = bf & (FF - 1);
    float* row = g_A + (size_t)bf * TT;
    const int tid = threadIdx.x;

    float v[16];
    #pragma unroll
    for (int i = 0; i < 16; i++) v[i] = row[tid + i * 256];

    float m = v[0];
    #pragma unroll
    for (int i = 1; i < 16; i++) m = fmaxf(m, v[i]);

    __shared__ float sred[8];
    #pragma unroll
    for (int o = 16; o > 0; o >>= 1) m = fmaxf(m, __shfl_xor_sync(0xffffffffu, m, o));
    if ((tid & 31) == 0) sred[tid >> 5] = m;
    __syncthreads();
    m = sred[0];
    #pragma unroll
    for (int w = 1; w < 8; w++) m = fmaxf(m, sred[w]);

    float s = 0.f;
    #pragma unroll
    for (int i = 0; i < 16; i++) { v[i] = __expf(v[i] - m); s += v[i]; }
    #pragma unroll
    for (int o = 16; o > 0; o >>= 1) s += __shfl_xor_sync(0xffffffffu, s, o);
    __syncthreads();
    if ((tid & 31) == 0) sred[tid >> 5] = s;
    __syncthreads();
    s = 0.f;
    #pragma unroll
    for (int w = 0; w < 8; w++) s += sred[w];

    float inv = __fdividef(1.f, s);

    float ts = (float)pow(1.0e-4, (double)(f & ~1) / 64.0);
    bool odd = (f & 1) != 0;
    #pragma unroll
    for (int i = 0; i < 16; i++) {
        int t = tid + i * 256;
        float ang = (float)t * ts;
        float pe = odd ? cosf(ang) : sinf(ang);
        row[t] = v[i] * inv + pe;
    }
}

// ---------------- Kernel 3: fused dense GEMM (FFMA2, t-pair packing) + sigmoid + partial T-sum ----
// Block tile: 128 t x 64 l per chunk, 4 chunks (512 t) per block. K=64.
// Thread tile: 8 t (4 packed t-pairs) x 4 l. 256 threads = 16 tgrp x 16 lgrp.
// A pairs come straight from smem (adjacent t = natural f32x2); W is pre-duplicated
// in smem so the b-operand is a natural f32x2 too -> ZERO pack movs in the k-loop.
__global__ __launch_bounds__(256, 2) void gemm_sig_reduce_kernel(
    const float* __restrict__ W,     // [F, L] = [64, 4096]
    const float* __restrict__ bias)  // [L]
{
    extern __shared__ __align__(16) float smem[];
    float (*Asm)[128]  = (float(*)[128])smem;             // 64 x 128 t  (32 KB)
    float (*Wdup)[128] = (float(*)[128])(smem + 64 * 128); // 64 x (64 l duplicated) (32 KB)

    const int tid  = threadIdx.x;
    const int tgrp = tid & 15;        // t-group: t_local = tgrp*8 .. +7
    const int lgrp = tid >> 4;        // l-group: l_local = lgrp*4 .. +3
    const int bid = blockIdx.x;
    const int lt  = bid & 63;
    const int b   = (bid >> 6) & 15;
    const int seg = bid >> 10;        // 0..7
    const int l0  = lt * 64;

    // Build duplicated W tile: Wdup[k][2j] = Wdup[k][2j+1] = W[k][l0+j]
    for (int i = tid; i < 64 * 64; i += 256) {
        int fr = i >> 6, c = i & 63;
        float w = W[(size_t)fr * LL + l0 + c];
        *(float2*)&Wdup[fr][2 * c] = make_float2(w, w);
    }

    // bias pairs (dup — both packed lanes are different t, same l)
    unsigned long long bp[4];
    #pragma unroll
    for (int j = 0; j < 4; j++) {
        float bv = bias[l0 + lgrp * 4 + j];
        bp[j] = packff(bv, bv);
    }

    float colsum[4] = {0.f, 0.f, 0.f, 0.f};

    const float* Ab = g_A + (size_t)b * FF * TT;

    for (int ch = 0; ch < 4; ch++) {
        const int t0 = seg * 512 + ch * 128;
        __syncthreads();   // prev chunk reads done; on ch=0 also fences Wdup writes
        {
            int r0 = tid >> 5;       // 0..7
            int c4 = tid & 31;       // 0..31
            #pragma unroll
            for (int r = 0; r < 8; r++) {
                int fr = r * 8 + r0;
                *(float4*)&Asm[fr][c4 * 4] = *(const float4*)&Ab[(size_t)fr * TT + t0 + c4 * 4];
            }
        }
        __syncthreads();

        unsigned long long acc[4][4];  // [l][tpair]
        #pragma unroll
        for (int j = 0; j < 4; j++)
            #pragma unroll
            for (int p = 0; p < 4; p++) acc[j][p] = bp[j];

        #pragma unroll 16
        for (int k = 0; k < 64; k++) {
            const ulonglong2* ap = (const ulonglong2*)&Asm[k][tgrp * 8];
            ulonglong2 A0 = ap[0];               // pairs (t0,t1) (t2,t3)
            ulonglong2 A1 = ap[1];               // pairs (t4,t5) (t6,t7)
            const ulonglong2* wp = (const ulonglong2*)&Wdup[k][lgrp * 8];
            ulonglong2 W0 = wp[0];               // dup(l0) dup(l1)
            ulonglong2 W1 = wp[1];               // dup(l2) dup(l3)
            ffma2(acc[0][0], A0.x, W0.x); ffma2(acc[0][1], A0.y, W0.x);
            ffma2(acc[0][2], A1.x, W0.x); ffma2(acc[0][3], A1.y, W0.x);
            ffma2(acc[1][0], A0.x, W0.y); ffma2(acc[1][1], A0.y, W0.y);
            ffma2(acc[1][2], A1.x, W0.y); ffma2(acc[1][3], A1.y, W0.y);
            ffma2(acc[2][0], A0.x, W1.x); ffma2(acc[2][1], A0.y, W1.x);
            ffma2(acc[2][2], A1.x, W1.x); ffma2(acc[2][3], A1.y, W1.x);
            ffma2(acc[3][0], A0.x, W1.y); ffma2(acc[3][1], A0.y, W1.y);
            ffma2(acc[3][2], A1.x, W1.y); ffma2(acc[3][3], A1.y, W1.y);
        }

        // sigmoid(y)*2-1 = (1-e^-y)/(1+e^-y); both packed lanes reduce into same l
        #pragma unroll
        for (int j = 0; j < 4; j++) {
            #pragma unroll
            for (int p = 0; p < 4; p++) {
                float ylo, yhi;
                unpackff(acc[j][p], ylo, yhi);
                float el = __expf(-ylo);
                float eh = __expf(-yhi);
                colsum[j] += __fdividef(1.f - el, 1.f + el)
                           + __fdividef(1.f - eh, 1.f + eh);
            }
        }
    }

    // block reduction over the 16 tgrp rows (deterministic, no atomics)
    __syncthreads();
    float* red = &Asm[0][0];          // reuse: 16 x 64 floats
    #pragma unroll
    for (int j = 0; j < 4; j++) red[tgrp * 64 + lgrp * 4 + j] = colsum[j];
    __syncthreads();
    #pragma unroll
    for (int s2 = 8; s2 > 0; s2 >>= 1) {
        if (tgrp < s2) {
            #pragma unroll
            for (int j = 0; j < 4; j++)
                red[tgrp * 64 + lgrp * 4 + j] += red[(tgrp + s2) * 64 + lgrp * 4 + j];
        }
        __syncthreads();
    }
    if (tgrp == 0) {
        #pragma unroll
        for (int j = 0; j < 4; j++)
            g_part[((size_t)seg * BB + b) * LL + l0 + lgrp * 4 + j] = red[lgrp * 4 + j];
    }
}

// ---------------- Kernel 4: Gaussian shifting layer (banded) ----------------
__global__ __launch_bounds__(256) void warp_out_kernel(
    const float* __restrict__ x,     // [B,T,C]
    float* __restrict__ out)         // [B,L,C]
{
    const int idx = blockIdx.x * 256 + threadIdx.x;   // b*L + l
    const int b = idx >> 12;
    const int l = idx & (LL - 1);

    float sh = 0.f;
    #pragma unroll
    for (int s = 0; s < TSEG; s++) sh += g_part[(size_t)s * BB * LL + idx];

    const float center = ((float)(l + 1) + sh) * ((float)TT / (float)LL);

    int tlo = (int)ceilf(center - 7.f);
    int thi = (int)floorf(center + 7.f);
    if (tlo < 1)  tlo = 1;
    if (thi > TT) thi = TT;

    float acc[8] = {0.f, 0.f, 0.f, 0.f, 0.f, 0.f, 0.f, 0.f};
    const float* xb = x + (size_t)b * TT * CC;
    for (int t = tlo; t <= thi; t++) {
        float d = (float)t - center;
        float w = __expf(-d * d);                     // WIDTH = 1
        const float4* xp = (const float4*)(xb + (size_t)(t - 1) * CC);
        float4 x0 = xp[0];
        float4 x1 = xp[1];
        acc[0] = fmaf(w, x0.x, acc[0]);
        acc[1] = fmaf(w, x0.y, acc[1]);
        acc[2] = fmaf(w, x0.z, acc[2]);
        acc[3] = fmaf(w, x0.w, acc[3]);
        acc[4] = fmaf(w, x1.x, acc[4]);
        acc[5] = fmaf(w, x1.y, acc[5]);
        acc[6] = fmaf(w, x1.z, acc[6]);
        acc[7] = fmaf(w, x1.w, acc[7]);
    }

    const float inv = (float)(1.0 / 1.772637204826652);   // 1/AMPLITUDE
    float4* op = (float4*)(out + (size_t)idx * CC);
    op[0] = make_float4(acc[0] * inv, acc[1] * inv, acc[2] * inv, acc[3] * inv);
    op[1] = make_float4(acc[4] * inv, acc[5] * inv, acc[6] * inv, acc[7] * inv);
}

// ---------------- launch ----------------
extern "C" void kernel_launch(void* const* d_in, const int* in_sizes, int n_in,
                              void* d_out, int out_size)
{
    const float* x       = (const float*)d_in[0];
    const float* conv_w  = (const float*)d_in[1];
    const float* conv_b  = (const float*)d_in[2];
    const float* gamma   = (const float*)d_in[3];
    const float* beta    = (const float*)d_in[4];
    const float* mean    = (const float*)d_in[5];
    const float* var     = (const float*)d_in[6];
    const float* dense_w = (const float*)d_in[7];
    const float* dense_b = (const float*)d_in[8];
    float* out = (float*)d_out;

    const int gemm_smem = 64 * 128 * sizeof(float) * 2;   // 64 KB dynamic
    cudaFuncSetAttribute(gemm_sig_reduce_kernel,
                         cudaFuncAttributeMaxDynamicSharedMemorySize, gemm_smem);

    conv_bn_kernel<<<dim3(TT / 256, BB), 256>>>(x, conv_w, conv_b, gamma, beta, mean, var);
    softmax_pe_kernel<<<BB * FF, 256>>>();
    gemm_sig_reduce_kernel<<<(LL / 64) * BB * TSEG, 256, gemm_smem>>>(dense_w, dense_b);
    warp_out_kernel<<<(BB * LL) / 256, 256>>>(x, out);
}

// round 5
// speedup vs baseline: 1.7077x; 1.7077x over previous
#include <cuda_runtime.h>
#include <math.h>

#define BB 16
#define TT 4096
#define CC 8
#define FF 64
#define KW 11
#define LL 4096
#define TSEG 8

// Scratch (device globals; no runtime allocation). 16B-aligned: accessed as float4.
__device__ __align__(16) float g_A[BB * FF * TT];        // 16 MB: conv+BN -> softmax+posenc, [B][F][T]
__device__ __align__(16) float g_part[TSEG * BB * LL];   // 2 MB: partial T-sums of sigmoid(dense)

// ---------------- f32x2 packed helpers (sm_103a FFMA2) ----------------
__device__ __forceinline__ unsigned long long packff(float lo, float hi) {
    unsigned long long r;
    asm("mov.b64 %0, {%1, %2};" : "=l"(r) : "f"(lo), "f"(hi));
    return r;
}
__device__ __forceinline__ void unpackff(unsigned long long v, float& lo, float& hi) {
    asm("mov.b64 {%0, %1}, %2;" : "=f"(lo), "=f"(hi) : "l"(v));
}
__device__ __forceinline__ void ffma2(unsigned long long& d, unsigned long long a, unsigned long long b) {
    asm("fma.rn.f32x2 %0, %1, %2, %0;" : "+l"(d) : "l"(a), "l"(b));
}

// ---------------- Kernel 1: Conv1D (SAME) + BatchNorm -> g_A[b][f][t] ----------------
__global__ __launch_bounds__(256) void conv_bn_kernel(
    const float* __restrict__ x,        // [B,T,C]
    const float* __restrict__ conv_w,   // [K,C,F]
    const float* __restrict__ conv_b,   // [F]
    const float* __restrict__ gamma,
    const float* __restrict__ beta,
    const float* __restrict__ mean,
    const float* __restrict__ var)
{
    __shared__ __align__(16) float ws[KW * CC * FF];
    __shared__ __align__(16) float xs[266][9];

    const int tid = threadIdx.x;
    const int b  = blockIdx.y;
    const int t0 = blockIdx.x * 256;

    for (int i = tid; i < (KW * CC * FF) / 4; i += 256)
        ((float4*)ws)[i] = ((const float4*)conv_w)[i];

    for (int i = tid; i < 266; i += 256) {
        int t = t0 + i - 5;
        if (t >= 0 && t < TT) {
            const float* xp = x + ((size_t)b * TT + t) * CC;
            #pragma unroll
            for (int c = 0; c < CC; c++) xs[i][c] = xp[c];
        } else {
            #pragma unroll
            for (int c = 0; c < CC; c++) xs[i][c] = 0.f;
        }
    }
    __syncthreads();

    const int t = t0 + tid;
    for (int fo = 0; fo < FF; fo += 8) {
        float acc[8];
        #pragma unroll
        for (int j = 0; j < 8; j++) acc[j] = conv_b[fo + j];
        #pragma unroll
        for (int k = 0; k < KW; k++) {
            #pragma unroll
            for (int c = 0; c < CC; c++) {
                float xv = xs[tid + k][c];
                const float* wp = &ws[(k * CC + c) * FF + fo];
                #pragma unroll
                for (int j = 0; j < 8; j++) acc[j] = fmaf(xv, wp[j], acc[j]);
            }
        }
        #pragma unroll
        for (int j = 0; j < 8; j++) {
            int f = fo + j;
            float inv = rsqrtf(var[f] + 1e-3f);
            float val = (acc[j] - mean[f]) * inv * gamma[f] + beta[f];
            g_A[((size_t)b * FF + f) * TT + t] = val;
        }
    }
}

// ---------------- Kernel 2: softmax over T (per b,f) + sine positional encoding ----------------
__global__ __launch_bounds__(256) void softmax_pe_kernel()
{
    const int bf = blockIdx.x;           // b*64 + f
    const int f  = bf & (FF - 1);
    float* row = g_A + (size_t)bf * TT;
    const int tid = threadIdx.x;

    float v[16];
    #pragma unroll
    for (int i = 0; i < 16; i++) v[i] = row[tid + i * 256];

    float m = v[0];
    #pragma unroll
    for (int i = 1; i < 16; i++) m = fmaxf(m, v[i]);

    __shared__ float sred[8];
    #pragma unroll
    for (int o = 16; o > 0; o >>= 1) m = fmaxf(m, __shfl_xor_sync(0xffffffffu, m, o));
    if ((tid & 31) == 0) sred[tid >> 5] = m;
    __syncthreads();
    m = sred[0];
    #pragma unroll
    for (int w = 1; w < 8; w++) m = fmaxf(m, sred[w]);

    float s = 0.f;
    #pragma unroll
    for (int i = 0; i < 16; i++) { v[i] = __expf(v[i] - m); s += v[i]; }
    #pragma unroll
    for (int o = 16; o > 0; o >>= 1) s += __shfl_xor_sync(0xffffffffu, s, o);
    __syncthreads();
    if ((tid & 31) == 0) sred[tid >> 5] = s;
    __syncthreads();
    s = 0.f;
    #pragma unroll
    for (int w = 0; w < 8; w++) s += sred[w];

    float inv = __fdividef(1.f, s);

    float ts = (float)pow(1.0e-4, (double)(f & ~1) / 64.0);
    bool odd = (f & 1) != 0;
    #pragma unroll
    for (int i = 0; i < 16; i++) {
        int t = tid + i * 256;
        float ang = (float)t * ts;
        float pe = odd ? cosf(ang) : sinf(ang);
        row[t] = v[i] * inv + pe;
    }
}

// ---------------- Kernel 3: fused dense GEMM (FFMA2, l-pair packing) + sigmoid + partial T-sum ----
// Block tile per chunk: 128 t x 128 l; 4 chunks (512 t) per block. K=64.
// Thread tile: 8 t x 8 l (4 natural l-pairs). 256 threads = 16 tgrp x 16 lgrp.
// W pairs come straight from Wsm (adjacent l = natural f32x2, NO duplication);
// A is broadcast-packed with one mov per value (8/k), amortized over 4 FFMA2 each.
// Per warp-k: 2048 B smem (16 cyc) vs 32 FFMA2 (16 cyc) -> balanced at roofline.
__global__ __launch_bounds__(256, 2) void gemm_sig_reduce_kernel(
    const float* __restrict__ W,     // [F, L] = [64, 4096]
    const float* __restrict__ bias)  // [L]
{
    extern __shared__ __align__(16) float smem[];
    float (*Asm)[128] = (float(*)[128])smem;               // 64 k x 128 t  (32 KB)
    float (*Wsm)[128] = (float(*)[128])(smem + 64 * 128);  // 64 k x 128 l  (32 KB)

    const int tid  = threadIdx.x;
    const int tgrp = tid & 15;        // t-group: t_local = tgrp*8 .. +7
    const int lgrp = tid >> 4;        // l-group: l_local = lgrp*8 .. +7
    const int bid = blockIdx.x;
    const int lt  = bid & 31;         // 32 l-tiles of 128
    const int b   = (bid >> 5) & 15;
    const int seg = bid >> 9;         // 0..7
    const int l0  = lt * 128;

    // load W tile once (64 x 128), contiguous float4
    for (int i = tid; i < (64 * 128) / 4; i += 256) {
        int fr = i >> 5;              // /32 float4 per row
        int c4 = i & 31;
        *(float4*)&Wsm[fr][c4 * 4] = *(const float4*)&W[(size_t)fr * LL + l0 + c4 * 4];
    }

    // bias pairs: natural adjacent-l pairs
    ulonglong2 bq0 = *(const ulonglong2*)&bias[l0 + lgrp * 8];
    ulonglong2 bq1 = *(const ulonglong2*)&bias[l0 + lgrp * 8 + 4];
    unsigned long long bp[4] = {bq0.x, bq0.y, bq1.x, bq1.y};

    float colsum[8];
    #pragma unroll
    for (int i = 0; i < 8; i++) colsum[i] = 0.f;

    const float* Ab = g_A + (size_t)b * FF * TT;

    for (int ch = 0; ch < 4; ch++) {
        const int t0 = seg * 512 + ch * 128;
        __syncthreads();   // prev chunk reads done; on ch=0 also fences Wsm writes
        {
            int r0 = tid >> 5;       // 0..7
            int c4 = tid & 31;       // 0..31
            #pragma unroll
            for (int r = 0; r < 8; r++) {
                int fr = r * 8 + r0;
                *(float4*)&Asm[fr][c4 * 4] = *(const float4*)&Ab[(size_t)fr * TT + t0 + c4 * 4];
            }
        }
        __syncthreads();

        unsigned long long acc[8][4];  // [t][lpair]
        #pragma unroll
        for (int i = 0; i < 8; i++)
            #pragma unroll
            for (int j = 0; j < 4; j++) acc[i][j] = bp[j];

        #pragma unroll 8
        for (int k = 0; k < 64; k++) {
            const ulonglong2* wq = (const ulonglong2*)&Wsm[k][lgrp * 8];
            ulonglong2 w01 = wq[0];                 // pairs (l0,l1) (l2,l3)
            ulonglong2 w23 = wq[1];                 // pairs (l4,l5) (l6,l7)
            float4 a0 = *(const float4*)&Asm[k][tgrp * 8];
            float4 a1 = *(const float4*)&Asm[k][tgrp * 8 + 4];
            float af[8] = {a0.x, a0.y, a0.z, a0.w, a1.x, a1.y, a1.z, a1.w};
            #pragma unroll
            for (int i = 0; i < 8; i++) {
                unsigned long long ap = packff(af[i], af[i]);
                ffma2(acc[i][0], ap, w01.x);
                ffma2(acc[i][1], ap, w01.y);
                ffma2(acc[i][2], ap, w23.x);
                ffma2(acc[i][3], ap, w23.y);
            }
        }

        // sigmoid(y)*2-1 = (1-e^-y)/(1+e^-y); lanes are adjacent l -> separate colsums
        #pragma unroll
        for (int i = 0; i < 8; i++) {
            #pragma unroll
            for (int j = 0; j < 4; j++) {
                float ylo, yhi;
                unpackff(acc[i][j], ylo, yhi);
                float el = __expf(-ylo);
                float eh = __expf(-yhi);
                colsum[2 * j]     += __fdividef(1.f - el, 1.f + el);
                colsum[2 * j + 1] += __fdividef(1.f - eh, 1.f + eh);
            }
        }
    }

    // block reduction over the 16 tgrp rows (deterministic, no atomics)
    __syncthreads();
    float* red = &smem[0];            // reuse: 16 x 128 floats
    #pragma unroll
    for (int i = 0; i < 8; i++) red[tgrp * 128 + lgrp * 8 + i] = colsum[i];
    __syncthreads();
    #pragma unroll
    for (int s2 = 8; s2 > 0; s2 >>= 1) {
        if (tgrp < s2) {
            #pragma unroll
            for (int i = 0; i < 8; i++)
                red[tgrp * 128 + lgrp * 8 + i] += red[(tgrp + s2) * 128 + lgrp * 8 + i];
        }
        __syncthreads();
    }
    if (tgrp == 0) {
        #pragma unroll
        for (int i = 0; i < 8; i++)
            g_part[((size_t)seg * BB + b) * LL + l0 + lgrp * 8 + i] = red[lgrp * 8 + i];
    }
}

// ---------------- Kernel 4: Gaussian shifting layer (banded) ----------------
__global__ __launch_bounds__(256) void warp_out_kernel(
    const float* __restrict__ x,     // [B,T,C]
    float* __restrict__ out)         // [B,L,C]
{
    const int idx = blockIdx.x * 256 + threadIdx.x;   // b*L + l
    const int b = idx >> 12;
    const int l = idx & (LL - 1);

    float sh = 0.f;
    #pragma unroll
    for (int s = 0; s < TSEG; s++) sh += g_part[(size_t)s * BB * LL + idx];

    const float center = ((float)(l + 1) + sh) * ((float)TT / (float)LL);

    int tlo = (int)ceilf(center - 7.f);
    int thi = (int)floorf(center + 7.f);
    if (tlo < 1)  tlo = 1;
    if (thi > TT) thi = TT;

    float acc[8] = {0.f, 0.f, 0.f, 0.f, 0.f, 0.f, 0.f, 0.f};
    const float* xb = x + (size_t)b * TT * CC;
    for (int t = tlo; t <= thi; t++) {
        float d = (float)t - center;
        float w = __expf(-d * d);                     // WIDTH = 1
        const float4* xp = (const float4*)(xb + (size_t)(t - 1) * CC);
        float4 x0 = xp[0];
        float4 x1 = xp[1];
        acc[0] = fmaf(w, x0.x, acc[0]);
        acc[1] = fmaf(w, x0.y, acc[1]);
        acc[2] = fmaf(w, x0.z, acc[2]);
        acc[3] = fmaf(w, x0.w, acc[3]);
        acc[4] = fmaf(w, x1.x, acc[4]);
        acc[5] = fmaf(w, x1.y, acc[5]);
        acc[6] = fmaf(w, x1.z, acc[6]);
        acc[7] = fmaf(w, x1.w, acc[7]);
    }

    const float inv = (float)(1.0 / 1.772637204826652);   // 1/AMPLITUDE
    float4* op = (float4*)(out + (size_t)idx * CC);
    op[0] = make_float4(acc[0] * inv, acc[1] * inv, acc[2] * inv, acc[3] * inv);
    op[1] = make_float4(acc[4] * inv, acc[5] * inv, acc[6] * inv, acc[7] * inv);
}

// ---------------- launch ----------------
extern "C" void kernel_launch(void* const* d_in, const int* in_sizes, int n_in,
                              void* d_out, int out_size)
{
    const float* x       = (const float*)d_in[0];
    const float* conv_w  = (const float*)d_in[1];
    const float* conv_b  = (const float*)d_in[2];
    const float* gamma   = (const float*)d_in[3];
    const float* beta    = (const float*)d_in[4];
    const float* mean    = (const float*)d_in[5];
    const float* var     = (const float*)d_in[6];
    const float* dense_w = (const float*)d_in[7];
    const float* dense_b = (const float*)d_in[8];
    float* out = (float*)d_out;

    const int gemm_smem = 64 * 128 * sizeof(float) * 2;   // 64 KB dynamic
    cudaFuncSetAttribute(gemm_sig_reduce_kernel,
                         cudaFuncAttributeMaxDynamicSharedMemorySize, gemm_smem);

    conv_bn_kernel<<<dim3(TT / 256, BB), 256>>>(x, conv_w, conv_b, gamma, beta, mean, var);
    softmax_pe_kernel<<<BB * FF, 256>>>();
    gemm_sig_reduce_kernel<<<(LL / 128) * BB * TSEG, 256, gemm_smem>>>(dense_w, dense_b);
    warp_out_kernel<<<(BB * LL) / 256, 256>>>(x, out);
}

// round 8
// speedup vs baseline: 2.1869x; 1.2806x over previous
#include <cuda_runtime.h>
#include <math.h>
#include <cstdint>

#define BB 16
#define TT 4096
#define CC 8
#define FF 64
#define KW 11
#define LL 4096
#define NTT 32            // t-tiles of 128 per batch

// Scratch (device globals; no runtime allocation)
__device__ __align__(16) float g_P[BB * FF * TT];       // 16 MB softmax (no posenc), [B][F][T]
__device__ __align__(16) float g_U[TT * LL];            // 64 MB: posenc@W + bias, [T][L]
__device__ __align__(16) float g_part[NTT * BB * LL];   // 8 MB partial T-sums

// ---------------- helpers ----------------
__device__ __forceinline__ unsigned long long packff(float lo, float hi) {
    unsigned long long r;
    asm("mov.b64 %0, {%1, %2};" : "=l"(r) : "f"(lo), "f"(hi));
    return r;
}
__device__ __forceinline__ void unpackff(unsigned long long v, float& lo, float& hi) {
    asm("mov.b64 {%0, %1}, %2;" : "=f"(lo), "=f"(hi) : "l"(v));
}
__device__ __forceinline__ void ffma2(unsigned long long& d, unsigned long long a, unsigned long long b) {
    asm("fma.rn.f32x2 %0, %1, %2, %0;" : "+l"(d) : "l"(a), "l"(b));
}
__device__ __forceinline__ float tf32r(float v) {
    uint32_t r;
    asm("cvt.rn.tf32.f32 %0, %1;" : "=r"(r) : "f"(v));
    return __uint_as_float(r);
}
__device__ __forceinline__ void mma_tf32(float c[4], const uint32_t a[4], const uint32_t b[2]) {
    asm volatile("mma.sync.aligned.m16n8k8.row.col.f32.tf32.tf32.f32 "
        "{%0,%1,%2,%3}, {%4,%5,%6,%7}, {%8,%9}, {%0,%1,%2,%3};"
        : "+f"(c[0]), "+f"(c[1]), "+f"(c[2]), "+f"(c[3])
        : "r"(a[0]), "r"(a[1]), "r"(a[2]), "r"(a[3]), "r"(b[0]), "r"(b[1]));
}

// ---------------- Kernel 1: Conv1D (SAME) + BatchNorm -> g_P[b][f][t] (pre-softmax) ----------------
__global__ __launch_bounds__(256) void conv_bn_kernel(
    const float* __restrict__ x, const float* __restrict__ conv_w,
    const float* __restrict__ conv_b, const float* __restrict__ gamma,
    const float* __restrict__ beta, const float* __restrict__ mean,
    const float* __restrict__ var)
{
    __shared__ __align__(16) float ws[KW * CC * FF];
    __shared__ __align__(16) float xs[266][9];

    const int tid = threadIdx.x;
    const int b  = blockIdx.y;
    const int t0 = blockIdx.x * 256;

    for (int i = tid; i < (KW * CC * FF) / 4; i += 256)
        ((float4*)ws)[i] = ((const float4*)conv_w)[i];

    for (int i = tid; i < 266; i += 256) {
        int t = t0 + i - 5;
        if (t >= 0 && t < TT) {
            const float* xp = x + ((size_t)b * TT + t) * CC;
            #pragma unroll
            for (int c = 0; c < CC; c++) xs[i][c] = xp[c];
        } else {
            #pragma unroll
            for (int c = 0; c < CC; c++) xs[i][c] = 0.f;
        }
    }
    __syncthreads();

    const int t = t0 + tid;
    for (int fo = 0; fo < FF; fo += 8) {
        float acc[8];
        #pragma unroll
        for (int j = 0; j < 8; j++) acc[j] = conv_b[fo + j];
        #pragma unroll
        for (int k = 0; k < KW; k++) {
            #pragma unroll
            for (int c = 0; c < CC; c++) {
                float xv = xs[tid + k][c];
                const float* wp = &ws[(k * CC + c) * FF + fo];
                #pragma unroll
                for (int j = 0; j < 8; j++) acc[j] = fmaf(xv, wp[j], acc[j]);
            }
        }
        #pragma unroll
        for (int j = 0; j < 8; j++) {
            int f = fo + j;
            float inv = rsqrtf(var[f] + 1e-3f);
            g_P[((size_t)b * FF + f) * TT + t] = (acc[j] - mean[f]) * inv * gamma[f] + beta[f];
        }
    }
}

// ---------------- Kernel 2: softmax over T (pure; posenc handled in U) ----------------
__global__ __launch_bounds__(256) void softmax_kernel()
{
    const int bf = blockIdx.x;
    float* row = g_P + (size_t)bf * TT;
    const int tid = threadIdx.x;

    float v[16];
    #pragma unroll
    for (int i = 0; i < 16; i++) v[i] = row[tid + i * 256];

    float m = v[0];
    #pragma unroll
    for (int i = 1; i < 16; i++) m = fmaxf(m, v[i]);

    __shared__ float sred[8];
    #pragma unroll
    for (int o = 16; o > 0; o >>= 1) m = fmaxf(m, __shfl_xor_sync(0xffffffffu, m, o));
    if ((tid & 31) == 0) sred[tid >> 5] = m;
    __syncthreads();
    m = sred[0];
    #pragma unroll
    for (int w = 1; w < 8; w++) m = fmaxf(m, sred[w]);

    float s = 0.f;
    #pragma unroll
    for (int i = 0; i < 16; i++) { v[i] = __expf(v[i] - m); s += v[i]; }
    #pragma unroll
    for (int o = 16; o > 0; o >>= 1) s += __shfl_xor_sync(0xffffffffu, s, o);
    __syncthreads();
    if ((tid & 31) == 0) sred[tid >> 5] = s;
    __syncthreads();
    s = 0.f;
    #pragma unroll
    for (int w = 0; w < 8; w++) s += sred[w];

    float inv = __fdividef(1.f, s);
    #pragma unroll
    for (int i = 0; i < 16; i++) row[tid + i * 256] = v[i] * inv;
}

// ---------------- Kernel 3: U = posenc @ W + bias (fp32 FFMA2, b-independent, once) ----------------
// grid: (LL/128) x (TT/512); block 256. Same structure as proven R5 GEMM.
__global__ __launch_bounds__(256, 2) void u_gemm_kernel(
    const float* __restrict__ W,     // [F, L]
    const float* __restrict__ bias)  // [L]
{
    extern __shared__ __align__(16) float smem[];
    float (*Asm)[128] = (float(*)[128])smem;               // 64 k x 128 t  (32 KB)
    float (*Wsm)[128] = (float(*)[128])(smem + 64 * 128);  // 64 k x 128 l  (32 KB)
    __shared__ float ts[FF];

    const int tid  = threadIdx.x;
    const int tgrp = tid & 15;
    const int lgrp = tid >> 4;
    const int l0   = blockIdx.x * 128;
    const int tseg = blockIdx.y;

    if (tid < FF)
        ts[tid] = (float)pow(1.0e-4, (double)(tid & ~1) / 64.0);

    for (int i = tid; i < (64 * 128) / 4; i += 256) {
        int fr = i >> 5;
        int c4 = i & 31;
        *(float4*)&Wsm[fr][c4 * 4] = *(const float4*)&W[(size_t)fr * LL + l0 + c4 * 4];
    }

    ulonglong2 bq0 = *(const ulonglong2*)&bias[l0 + lgrp * 8];
    ulonglong2 bq1 = *(const ulonglong2*)&bias[l0 + lgrp * 8 + 4];
    unsigned long long bp[4] = {bq0.x, bq0.y, bq1.x, bq1.y};

    for (int ch = 0; ch < 4; ch++) {
        const int t0 = tseg * 512 + ch * 128;
        __syncthreads();
        // analytic posenc tile: Asm[k][t] = sin/cos((t0+t) * ts[k])
        for (int i = tid; i < 64 * 128; i += 256) {
            int k = i >> 7, t = i & 127;
            float ang = (float)(t0 + t) * ts[k];
            Asm[k][t] = (k & 1) ? cosf(ang) : sinf(ang);
        }
        __syncthreads();

        unsigned long long acc[8][4];
        #pragma unroll
        for (int i = 0; i < 8; i++)
            #pragma unroll
            for (int j = 0; j < 4; j++) acc[i][j] = bp[j];

        #pragma unroll 8
        for (int k = 0; k < 64; k++) {
            const ulonglong2* wq = (const ulonglong2*)&Wsm[k][lgrp * 8];
            ulonglong2 w01 = wq[0];
            ulonglong2 w23 = wq[1];
            float4 a0 = *(const float4*)&Asm[k][tgrp * 8];
            float4 a1 = *(const float4*)&Asm[k][tgrp * 8 + 4];
            float af[8] = {a0.x, a0.y, a0.z, a0.w, a1.x, a1.y, a1.z, a1.w};
            #pragma unroll
            for (int i = 0; i < 8; i++) {
                unsigned long long ap = packff(af[i], af[i]);
                ffma2(acc[i][0], ap, w01.x);
                ffma2(acc[i][1], ap, w01.y);
                ffma2(acc[i][2], ap, w23.x);
                ffma2(acc[i][3], ap, w23.y);
            }
        }

        #pragma unroll
        for (int i = 0; i < 8; i++) {
            float v0, v1, v2, v3, v4, v5, v6, v7;
            unpackff(acc[i][0], v0, v1);
            unpackff(acc[i][1], v2, v3);
            unpackff(acc[i][2], v4, v5);
            unpackff(acc[i][3], v6, v7);
            float* up = &g_U[(size_t)(t0 + tgrp * 8 + i) * LL + l0 + lgrp * 8];
            *(float4*)up       = make_float4(v0, v1, v2, v3);
            *(float4*)(up + 4) = make_float4(v4, v5, v6, v7);
        }
    }
}

// ---------------- Kernel 4: S = softmax @ W via mma.sync tf32; y = S + U; sigmoid; T-sum ----------------
// grid (b=16, ltile=32, ttile=32); block 256 = 8 warps (4 t-warps x 2 l-warps).
// Block tile 128t x 128l, K=64. Warp tile 32t x 64l = 2 m16 x 8 n8, 8 k-steps.
#define PS 68     // Psm row stride (mod 32 == 4 -> conflict-free A frags)
#define WS 136    // Wsm row stride (mod 32 == 8 -> conflict-free B frags)
#define SG_SMEM ((128 * PS + 64 * WS) * 4)

__global__ __launch_bounds__(256, 2) void sgemm_tc_kernel(const float* __restrict__ W)
{
    extern __shared__ __align__(16) float sm[];
    float* Psm = sm;                  // [128 t][PS]  (tf32-rounded softmax)
    float* Wsm = sm + 128 * PS;       // [64 k][WS]   (tf32-rounded W)

    const int tid = threadIdx.x;
    const int b     = blockIdx.x;
    const int l0    = blockIdx.y * 128;
    const int ttile = blockIdx.z;
    const int t0    = ttile * 128;

    // fill Psm (coalesced read along t, transposed store)
    for (int i = tid; i < 128 * 64; i += 256) {
        int f = i >> 7, t = i & 127;
        float v = g_P[((size_t)b * FF + f) * TT + t0 + t];
        Psm[t * PS + f] = tf32r(v);
    }
    // fill Wsm (coalesced)
    for (int i = tid; i < 64 * 128; i += 256) {
        int k = i >> 7, l = i & 127;
        Wsm[k * WS + l] = tf32r(W[(size_t)k * LL + l0 + l]);
    }
    __syncthreads();

    const int lane = tid & 31;
    const int w    = tid >> 5;
    const int wt   = w & 3;           // t-warp 0..3
    const int wl   = w >> 2;          // l-warp 0..1
    const int g    = lane >> 2;       // groupID 0..7
    const int tq   = lane & 3;        // thread-in-group 0..3

    float acc[2][8][4];
    #pragma unroll
    for (int m = 0; m < 2; m++)
        #pragma unroll
        for (int n = 0; n < 8; n++)
            #pragma unroll
            for (int j = 0; j < 4; j++) acc[m][n][j] = 0.f;

    const float* Pb = Psm + (wt * 32 + g) * PS + tq;
    const float* Bb = Wsm + tq * WS + wl * 64 + g;

    #pragma unroll
    for (int ks = 0; ks < 8; ks++) {
        uint32_t afr[2][4];
        #pragma unroll
        for (int m = 0; m < 2; m++) {
            const float* p = Pb + m * 16 * PS + ks * 8;
            afr[m][0] = __float_as_uint(p[0]);
            afr[m][1] = __float_as_uint(p[8 * PS]);
            afr[m][2] = __float_as_uint(p[4]);
            afr[m][3] = __float_as_uint(p[8 * PS + 4]);
        }
        #pragma unroll
        for (int n = 0; n < 8; n++) {
            uint32_t bfr[2];
            const float* q = Bb + ks * 8 * WS + n * 8;
            bfr[0] = __float_as_uint(q[0]);
            bfr[1] = __float_as_uint(q[4 * WS]);
            mma_tf32(acc[0][n], afr[0], bfr);
            mma_tf32(acc[1][n], afr[1], bfr);
        }
    }

    // epilogue: y = acc + U; d = (1-e^-y)/(1+e^-y); accumulate over t
    float colsum[16];
    #pragma unroll
    for (int i = 0; i < 16; i++) colsum[i] = 0.f;

    const int tbase = t0 + wt * 32 + g;
    const int cbase = l0 + wl * 64 + 2 * tq;
    #pragma unroll
    for (int m = 0; m < 2; m++) {
        #pragma unroll
        for (int n = 0; n < 8; n++) {
            int col = cbase + n * 8;
            float2 u0 = *(const float2*)&g_U[(size_t)(tbase + m * 16) * LL + col];
            float2 u1 = *(const float2*)&g_U[(size_t)(tbase + m * 16 + 8) * LL + col];
            float y00 = acc[m][n][0] + u0.x;
            float y01 = acc[m][n][1] + u0.y;
            float y10 = acc[m][n][2] + u1.x;
            float y11 = acc[m][n][3] + u1.y;
            float e;
            e = __expf(-y00); colsum[2 * n]     += __fdividef(1.f - e, 1.f + e);
            e = __expf(-y10); colsum[2 * n]     += __fdividef(1.f - e, 1.f + e);
            e = __expf(-y01); colsum[2 * n + 1] += __fdividef(1.f - e, 1.f + e);
            e = __expf(-y11); colsum[2 * n + 1] += __fdividef(1.f - e, 1.f + e);
        }
    }

    // reduce over g (lanes differing in bits 2..4)
    #pragma unroll
    for (int off = 4; off <= 16; off <<= 1)
        #pragma unroll
        for (int i = 0; i < 16; i++)
            colsum[i] += __shfl_xor_sync(0xffffffffu, colsum[i], off);

    __syncthreads();                  // done reading Psm/Wsm; reuse as reduce buffer
    float* red = sm;                  // [4 wt][128 l]
    if (g == 0) {
        #pragma unroll
        for (int n = 0; n < 8; n++) {
            red[wt * 128 + wl * 64 + n * 8 + 2 * tq]     = colsum[2 * n];
            red[wt * 128 + wl * 64 + n * 8 + 2 * tq + 1] = colsum[2 * n + 1];
        }
    }
    __syncthreads();
    if (tid < 128) {
        float s = red[tid] + red[128 + tid] + red[256 + tid] + red[384 + tid];
        g_part[((size_t)ttile * BB + b) * LL + l0 + tid] = s;
    }
}

// ---------------- Kernel 5: Gaussian shifting layer (banded) ----------------
__global__ __launch_bounds__(256) void warp_out_kernel(
    const float* __restrict__ x, float* __restrict__ out)
{
    const int idx = blockIdx.x * 256 + threadIdx.x;   // b*L + l
    const int b = idx >> 12;
    const int l = idx & (LL - 1);

    float sh = 0.f;
    #pragma unroll
    for (int s = 0; s < NTT; s++) sh += g_part[(size_t)s * BB * LL + idx];

    const float center = ((float)(l + 1) + sh) * ((float)TT / (float)LL);

    int tlo = (int)ceilf(center - 7.f);
    int thi = (int)floorf(center + 7.f);
    if (tlo < 1)  tlo = 1;
    if (thi > TT) thi = TT;

    float acc[8] = {0.f, 0.f, 0.f, 0.f, 0.f, 0.f, 0.f, 0.f};
    const float* xb = x + (size_t)b * TT * CC;
    for (int t = tlo; t <= thi; t++) {
        float d = (float)t - center;
        float wgt = __expf(-d * d);
        const float4* xp = (const float4*)(xb + (size_t)(t - 1) * CC);
        float4 x0 = xp[0];
        float4 x1 = xp[1];
        acc[0] = fmaf(wgt, x0.x, acc[0]);
        acc[1] = fmaf(wgt, x0.y, acc[1]);
        acc[2] = fmaf(wgt, x0.z, acc[2]);
        acc[3] = fmaf(wgt, x0.w, acc[3]);
        acc[4] = fmaf(wgt, x1.x, acc[4]);
        acc[5] = fmaf(wgt, x1.y, acc[5]);
        acc[6] = fmaf(wgt, x1.z, acc[6]);
        acc[7] = fmaf(wgt, x1.w, acc[7]);
    }

    const float inv = (float)(1.0 / 1.772637204826652);
    float4* op = (float4*)(out + (size_t)idx * CC);
    op[0] = make_float4(acc[0] * inv, acc[1] * inv, acc[2] * inv, acc[3] * inv);
    op[1] = make_float4(acc[4] * inv, acc[5] * inv, acc[6] * inv, acc[7] * inv);
}

// ---------------- launch ----------------
extern "C" void kernel_launch(void* const* d_in, const int* in_sizes, int n_in,
                              void* d_out, int out_size)
{
    const float* x       = (const float*)d_in[0];
    const float* conv_w  = (const float*)d_in[1];
    const float* conv_b  = (const float*)d_in[2];
    const float* gamma   = (const float*)d_in[3];
    const float* beta    = (const float*)d_in[4];
    const float* mean    = (const float*)d_in[5];
    const float* var     = (const float*)d_in[6];
    const float* dense_w = (const float*)d_in[7];
    const float* dense_b = (const float*)d_in[8];
    float* out = (float*)d_out;

    const int u_smem = 64 * 128 * sizeof(float) * 2;   // 64 KB
    cudaFuncSetAttribute(u_gemm_kernel,
                         cudaFuncAttributeMaxDynamicSharedMemorySize, u_smem);
    cudaFuncSetAttribute(sgemm_tc_kernel,
                         cudaFuncAttributeMaxDynamicSharedMemorySize, SG_SMEM);

    conv_bn_kernel<<<dim3(TT / 256, BB), 256>>>(x, conv_w, conv_b, gamma, beta, mean, var);
    softmax_kernel<<<BB * FF, 256>>>();
    u_gemm_kernel<<<dim3(LL / 128, TT / 512), 256, u_smem>>>(dense_w, dense_b);
    sgemm_tc_kernel<<<dim3(BB, LL / 128, TT / 128), 256, SG_SMEM>>>(dense_w);
    warp_out_kernel<<<(BB * LL) / 256, 256>>>(x, out);
}